// round 4
// baseline (speedup 1.0000x reference)
#include <cuda_runtime.h>
#include <math.h>

#define NB 16384
#define ND 16
#define KNN 25
#define LAMBDA_TSA 0.1f
#define NQUART 4
#define QTILE 64
#define CQUART (NB / NQUART)

// ---------------- device scratch (no allocations allowed) ----------------
__device__ float g_sq[NB];
__device__ int   g_nbrs[NB][KNN];
__device__ float g_pd[NQUART][KNN][NB];   // partial top-k dists (transposed)
__device__ int   g_pi[NQUART][KNN][NB];   // partial top-k indices
__device__ float g_acc_recon;
__device__ float g_acc_tsa;

// ---------------- kernel 1: squared norms + zero accumulators ----------------
__global__ void k_setup(const float* __restrict__ raw) {
    int i = blockIdx.x * blockDim.x + threadIdx.x;
    if (i < NB) {
        const float4* r4 = reinterpret_cast<const float4*>(raw + (size_t)i * ND);
        float s = 0.f;
#pragma unroll
        for (int j = 0; j < 4; ++j) {
            float4 v = r4[j];
            s = fmaf(v.x, v.x, s); s = fmaf(v.y, v.y, s);
            s = fmaf(v.z, v.z, s); s = fmaf(v.w, v.w, s);
        }
        g_sq[i] = s;
    }
    if (i == 0) { g_acc_recon = 0.f; g_acc_tsa = 0.f; }
}

// ---------------- kernel 2: recon MSE sum ----------------
__global__ void k_recon(const float* __restrict__ o, const float* __restrict__ t) {
    const float4* o4 = reinterpret_cast<const float4*>(o);
    const float4* t4 = reinterpret_cast<const float4*>(t);
    const int n4 = NB * ND / 4;
    float s = 0.f;
    for (int idx = blockIdx.x * blockDim.x + threadIdx.x; idx < n4;
         idx += gridDim.x * blockDim.x) {
        float4 a = o4[idx], b = t4[idx];
        float dx = a.x - b.x, dy = a.y - b.y, dz = a.z - b.z, dw = a.w - b.w;
        s = fmaf(dx, dx, s); s = fmaf(dy, dy, s);
        s = fmaf(dz, dz, s); s = fmaf(dw, dw, s);
    }
#pragma unroll
    for (int off = 16; off; off >>= 1) s += __shfl_xor_sync(0xffffffffu, s, off);
    __shared__ float ws[8];
    int lane = threadIdx.x & 31, wid = threadIdx.x >> 5;
    if (lane == 0) ws[wid] = s;
    __syncthreads();
    if (threadIdx.x == 0) {
        float tot = 0.f;
#pragma unroll
        for (int k = 0; k < 8; ++k) tot += ws[k];
        atomicAdd(&g_acc_recon, tot);
    }
}

// ---------------- top-k insert (register resident) ----------------
__device__ __forceinline__ void topk_insert(float (&bd)[KNN], int (&bi)[KNN],
                                            float& worst, float d2, int cg) {
    if (d2 < worst) {
        bool done = false;
#pragma unroll
        for (int kk = 0; kk < KNN; ++kk) {
            if (!done && bd[kk] == worst) { bd[kk] = d2; bi[kk] = cg; done = true; }
        }
        float w = -3.402823466e+38f;
#pragma unroll
        for (int kk = 0; kk < KNN; ++kk) w = fmaxf(w, bd[kk]);
        worst = w;
    }
}

// ---------------- kernel 3: partial KNN --------------------------------------
// grid = (256 query tiles of 64) x (4 candidate quarters of 4096), 256 threads.
// Each thread: 4x4 GEMM micro-tile; top-k over 16 candidates/tile (4 thr/query).
// In-block merge of the 4 per-query partials -> g_pd/g_pi[quarter].
#define KNN_SM_FLOATS 9600   // max(GEMM phase 6272, merge staging 9600)
__global__ void __launch_bounds__(256) k_knn(const float* __restrict__ raw) {
    __shared__ float sm[KNN_SM_FLOATS];
    float* Qs   = sm;                 // [16][64] d-major
    float* Cs   = sm + 1024;          // [16][64] d-major
    float* sqC  = sm + 2048;          // [64]
    float* Dist = sm + 2112;          // [64][65]

    const int tid    = threadIdx.x;
    const int qbase  = blockIdx.x * QTILE;
    const int cstart = blockIdx.y * CQUART;
    const float4* raw4 = reinterpret_cast<const float4*>(raw);

    // load & transpose query tile
    {
        int q = tid >> 2, dc = tid & 3;
        float4 v = raw4[(size_t)(qbase + q) * 4 + dc];
        Qs[(dc * 4 + 0) * 64 + q] = v.x;
        Qs[(dc * 4 + 1) * 64 + q] = v.y;
        Qs[(dc * 4 + 2) * 64 + q] = v.z;
        Qs[(dc * 4 + 3) * 64 + q] = v.w;
    }

    float bd[KNN];
    int   bi[KNN];
#pragma unroll
    for (int k = 0; k < KNN; ++k) { bd[k] = 3.402823466e+38f; bi[k] = 0; }
    float worst = 3.402823466e+38f;

    const int myq    = tid & 63;          // scan: query within tile
    const int cgroup = tid >> 6;          // scan: which 16-candidate slice
    const int qglob  = qbase + myq;
    const int clo    = cgroup * 16;

    const int q0 = (tid >> 4) * 4;        // GEMM micro-tile origin
    const int c0 = (tid & 15) * 4;

    for (int tile = 0; tile < CQUART / 64; ++tile) {
        const int cbase = cstart + tile * 64;
        __syncthreads();  // previous scan reads done before overwriting Cs/Dist

        {   // load & transpose candidate tile
            int c = tid >> 2, dc = tid & 3;
            float4 v = raw4[(size_t)(cbase + c) * 4 + dc];
            Cs[(dc * 4 + 0) * 64 + c] = v.x;
            Cs[(dc * 4 + 1) * 64 + c] = v.y;
            Cs[(dc * 4 + 2) * 64 + c] = v.z;
            Cs[(dc * 4 + 3) * 64 + c] = v.w;
        }
        if (tid < 64) sqC[tid] = g_sq[cbase + tid];
        __syncthreads();

        // 64x64 distance tile
        float acc[4][4];
#pragma unroll
        for (int i = 0; i < 4; ++i)
#pragma unroll
            for (int j = 0; j < 4; ++j) acc[i][j] = 0.f;

#pragma unroll
        for (int d = 0; d < 16; ++d) {
            float4 qa = *reinterpret_cast<const float4*>(Qs + d * 64 + q0);
            float4 ca = *reinterpret_cast<const float4*>(Cs + d * 64 + c0);
            float qv[4] = {qa.x, qa.y, qa.z, qa.w};
            float cv[4] = {ca.x, ca.y, ca.z, ca.w};
#pragma unroll
            for (int i = 0; i < 4; ++i)
#pragma unroll
                for (int j = 0; j < 4; ++j) acc[i][j] = fmaf(qv[i], cv[j], acc[i][j]);
        }
        float sc[4];
#pragma unroll
        for (int j = 0; j < 4; ++j) sc[j] = sqC[c0 + j];
#pragma unroll
        for (int i = 0; i < 4; ++i)
#pragma unroll
            for (int j = 0; j < 4; ++j)
                Dist[(q0 + i) * 65 + (c0 + j)] = fmaf(-2.f, acc[i][j], sc[j]);
        __syncthreads();

        // top-k scan: 16 candidates per thread, conflict-free (stride 65)
        const float* drow = Dist + myq * 65;
#pragma unroll 4
        for (int c = clo; c < clo + 16; ++c) {
            float d2 = drow[c];
            int cg = cbase + c;
            if (cg != qglob) topk_insert(bd, bi, worst, d2, cg);
        }
    }

    // in-block merge: 4 partial lists per query -> one top-25 per query
    __syncthreads();
    float* st_d = sm;                                   // [3][64][25] floats
    int*   st_i = reinterpret_cast<int*>(sm + 4800);    // [3][64][25] ints
    if (cgroup > 0) {
        int base = ((cgroup - 1) * 64 + myq) * KNN;
#pragma unroll
        for (int k = 0; k < KNN; ++k) { st_d[base + k] = bd[k]; st_i[base + k] = bi[k]; }
    }
    __syncthreads();
    if (cgroup == 0) {
        for (int g = 0; g < 3; ++g) {
            int base = (g * 64 + myq) * KNN;
#pragma unroll
            for (int k = 0; k < KNN; ++k)
                topk_insert(bd, bi, worst, st_d[base + k], st_i[base + k]);
        }
#pragma unroll
        for (int k = 0; k < KNN; ++k) {
            g_pd[blockIdx.y][k][qglob] = bd[k];
            g_pi[blockIdx.y][k][qglob] = bi[k];
        }
    }
}

// ---------------- kernel 3b: cross-quarter merge -----------------------------
__global__ void k_merge() {
    int q = blockIdx.x * blockDim.x + threadIdx.x;
    if (q >= NB) return;
    float bd[KNN];
    int   bi[KNN];
#pragma unroll
    for (int k = 0; k < KNN; ++k) { bd[k] = 3.402823466e+38f; bi[k] = 0; }
    float worst = 3.402823466e+38f;
#pragma unroll 1
    for (int qt = 0; qt < NQUART; ++qt)
#pragma unroll
        for (int k = 0; k < KNN; ++k)
            topk_insert(bd, bi, worst, g_pd[qt][k][q], g_pi[qt][k][q]);
#pragma unroll
    for (int k = 0; k < KNN; ++k) g_nbrs[q][k] = bi[k];
}

// ---------------- kernel 4: per-point TSA term (warp per point) --------------
// P=1: sum((Pz-Px)^2) = 2 - 2*(u.v)^2 with u,v unit top-eigenvectors.
#define TSA_WPB 8
__global__ void __launch_bounds__(256) k_tsa(const float* __restrict__ latent,
                                             const float* __restrict__ raw) {
    __shared__ float s_pts[TSA_WPB][KNN][ND];
    __shared__ float s_A[TSA_WPB][16 * 17];
    __shared__ float s_B[TSA_WPB][16 * 17];
    __shared__ float s_u[TSA_WPB][16];
    __shared__ float s_v[TSA_WPB][16];
    __shared__ float s_mu[TSA_WPB][16];
    __shared__ int   s_nb[TSA_WPB][KNN];

    const int w = threadIdx.x >> 5, lane = threadIdx.x & 31;
    const int i = blockIdx.x * TSA_WPB + w;

    if (lane < KNN) s_nb[w][lane] = g_nbrs[i][lane];
    __syncwarp();

    for (int p = 0; p < 2; ++p) {
        const float* src = p ? raw : latent;
        float* uvec = p ? s_v[w] : s_u[w];

        for (int idx = lane; idx < KNN * ND; idx += 32) {
            int k = idx >> 4, d = idx & 15;
            s_pts[w][k][d] = src[(size_t)s_nb[w][k] * ND + d];
        }
        __syncwarp();
        if (lane < 16) {
            float m = 0.f;
#pragma unroll
            for (int k = 0; k < KNN; ++k) m += s_pts[w][k][lane];
            s_mu[w][lane] = m * (1.f / KNN);
        }
        __syncwarp();
        for (int idx = lane; idx < KNN * ND; idx += 32) {
            int k = idx >> 4, d = idx & 15;
            s_pts[w][k][d] -= s_mu[w][d];
        }
        __syncwarp();
        for (int e = lane; e < 256; e += 32) {
            int a = e >> 4, b = e & 15;
            float s = 0.f;
#pragma unroll
            for (int k = 0; k < KNN; ++k) s = fmaf(s_pts[w][k][a], s_pts[w][k][b], s);
            s_A[w][a * 17 + b] = s;
        }
        __syncwarp();

        float* Ain = s_A[w];
        float* Aou = s_B[w];
#pragma unroll 1
        for (int sq = 0; sq < 8; ++sq) {
            for (int e = lane; e < 256; e += 32) {
                int a = e >> 4, b = e & 15;
                float s = 0.f;
#pragma unroll
                for (int k = 0; k < 16; ++k) s = fmaf(Ain[a * 17 + k], Ain[k * 17 + b], s);
                Aou[a * 17 + b] = s;
            }
            __syncwarp();
            float dv = (lane < 16) ? Aou[lane * 17 + lane] : 0.f;
#pragma unroll
            for (int off = 16; off; off >>= 1)
                dv = fmaxf(dv, __shfl_xor_sync(0xffffffffu, dv, off));
            float inv = 1.f / dv;
            for (int e = lane; e < 256; e += 32) {
                int a = e >> 4, b = e & 15;
                Aou[a * 17 + b] *= inv;
            }
            __syncwarp();
            float* tmp = Ain; Ain = Aou; Aou = tmp;
        }

        float bv = (lane < 16) ? Ain[lane * 17 + lane] : -1.f;
        int   bx = (lane < 16) ? lane : 1000;
#pragma unroll
        for (int off = 16; off; off >>= 1) {
            float ov = __shfl_xor_sync(0xffffffffu, bv, off);
            int   oi = __shfl_xor_sync(0xffffffffu, bx, off);
            if (ov > bv || (ov == bv && oi < bx)) { bv = ov; bx = oi; }
        }
        float uv = (lane < 16) ? Ain[lane * 17 + bx] : 0.f;
        float ss = uv * uv;
#pragma unroll
        for (int off = 16; off; off >>= 1) ss += __shfl_xor_sync(0xffffffffu, ss, off);
        float rn = rsqrtf(ss);
        if (lane < 16) uvec[lane] = uv * rn;
        __syncwarp();
    }

    float pd = (lane < 16) ? s_u[w][lane] * s_v[w][lane] : 0.f;
#pragma unroll
    for (int off = 16; off; off >>= 1) pd += __shfl_xor_sync(0xffffffffu, pd, off);
    if (lane == 0) {
        float term = fmaf(-2.f * pd, pd, 2.f);
        atomicAdd(&g_acc_tsa, term);
    }
}

// ---------------- kernel 5: finalize ----------------
__global__ void k_final(float* __restrict__ out) {
    out[0] = g_acc_recon * (1.f / (NB * ND)) + LAMBDA_TSA * g_acc_tsa * (1.f / NB);
}

// ---------------- launcher (kernel launches only; graph-capturable) ----------
extern "C" void kernel_launch(void* const* d_in, const int* in_sizes, int n_in,
                              void* d_out, int out_size) {
    const float* outputs = (const float*)d_in[0];
    const float* targets = (const float*)d_in[1];
    const float* latent  = (const float*)d_in[2];
    const float* raw     = (const float*)d_in[3];
    float* out = (float*)d_out;

    k_setup<<<NB / 256, 256>>>(raw);
    k_recon<<<64, 256>>>(outputs, targets);
    k_knn<<<dim3(NB / QTILE, NQUART), 256>>>(raw);
    k_merge<<<NB / 256, 256>>>();
    k_tsa<<<NB / TSA_WPB, 256>>>(latent, raw);
    k_final<<<1, 1>>>(out);
}

// round 5
// speedup vs baseline: 22.5573x; 22.5573x over previous
#include <cuda_runtime.h>
#include <math.h>

#define NB 16384
#define ND 16
#define KNN 25
#define LAMBDA_TSA 0.1f
#define FULLM 0xffffffffu

// ---------------- device scratch (no allocations allowed) ----------------
__device__ float g_sq[NB];
__device__ float g_dist[NB][NB];          // 1 GiB distance matrix scratch
__device__ int   g_nbrs[NB][KNN];
__device__ float g_acc_recon;
__device__ float g_acc_tsa;

// ---------------- kernel 1: squared norms + zero accumulators ----------------
__global__ void k_setup(const float* __restrict__ raw) {
    int i = blockIdx.x * blockDim.x + threadIdx.x;
    if (i < NB) {
        const float4* r4 = reinterpret_cast<const float4*>(raw + (size_t)i * ND);
        float s = 0.f;
#pragma unroll
        for (int j = 0; j < 4; ++j) {
            float4 v = r4[j];
            s = fmaf(v.x, v.x, s); s = fmaf(v.y, v.y, s);
            s = fmaf(v.z, v.z, s); s = fmaf(v.w, v.w, s);
        }
        g_sq[i] = s;
    }
    if (i == 0) { g_acc_recon = 0.f; g_acc_tsa = 0.f; }
}

// ---------------- kernel 2: recon MSE sum ----------------
__global__ void k_recon(const float* __restrict__ o, const float* __restrict__ t) {
    const float4* o4 = reinterpret_cast<const float4*>(o);
    const float4* t4 = reinterpret_cast<const float4*>(t);
    const int n4 = NB * ND / 4;
    float s = 0.f;
    for (int idx = blockIdx.x * blockDim.x + threadIdx.x; idx < n4;
         idx += gridDim.x * blockDim.x) {
        float4 a = o4[idx], b = t4[idx];
        float dx = a.x - b.x, dy = a.y - b.y, dz = a.z - b.z, dw = a.w - b.w;
        s = fmaf(dx, dx, s); s = fmaf(dy, dy, s);
        s = fmaf(dz, dz, s); s = fmaf(dw, dw, s);
    }
#pragma unroll
    for (int off = 16; off; off >>= 1) s += __shfl_xor_sync(FULLM, s, off);
    __shared__ float ws[8];
    int lane = threadIdx.x & 31, wid = threadIdx.x >> 5;
    if (lane == 0) ws[wid] = s;
    __syncthreads();
    if (threadIdx.x == 0) {
        float tot = 0.f;
#pragma unroll
        for (int k = 0; k < 8; ++k) tot += ws[k];
        atomicAdd(&g_acc_recon, tot);
    }
}

// ---------------- kernel 3: distance matrix GEMM -----------------------------
// 128x128 tile per block, 256 threads, 8x8 micro-tile. d2'[q][c]=sqC[c]-2*dot.
// (row-constant sq[q] omitted: does not change per-row ordering)
__global__ void __launch_bounds__(256) k_dist(const float* __restrict__ raw) {
    __shared__ float Qs[16 * 128];
    __shared__ float Cs[16 * 128];
    __shared__ float sqC[128];

    const int tid   = threadIdx.x;
    const int qbase = blockIdx.y * 128;
    const int cbase = blockIdx.x * 128;
    const float4* raw4 = reinterpret_cast<const float4*>(raw);

    // load & transpose tiles (d-major)
    for (int f = tid; f < 512; f += 256) {
        int p = f >> 2, dc = f & 3;
        float4 vq = raw4[(size_t)(qbase + p) * 4 + dc];
        Qs[(dc * 4 + 0) * 128 + p] = vq.x;
        Qs[(dc * 4 + 1) * 128 + p] = vq.y;
        Qs[(dc * 4 + 2) * 128 + p] = vq.z;
        Qs[(dc * 4 + 3) * 128 + p] = vq.w;
        float4 vc = raw4[(size_t)(cbase + p) * 4 + dc];
        Cs[(dc * 4 + 0) * 128 + p] = vc.x;
        Cs[(dc * 4 + 1) * 128 + p] = vc.y;
        Cs[(dc * 4 + 2) * 128 + p] = vc.z;
        Cs[(dc * 4 + 3) * 128 + p] = vc.w;
    }
    if (tid < 128) sqC[tid] = g_sq[cbase + tid];
    __syncthreads();

    const int q0 = (tid >> 4) * 8, c0 = (tid & 15) * 8;

    float acc[8][8];
#pragma unroll
    for (int i = 0; i < 8; ++i)
#pragma unroll
        for (int j = 0; j < 8; ++j) acc[i][j] = 0.f;

#pragma unroll
    for (int d = 0; d < 16; ++d) {
        float4 qa = *reinterpret_cast<const float4*>(Qs + d * 128 + q0);
        float4 qb = *reinterpret_cast<const float4*>(Qs + d * 128 + q0 + 4);
        float4 ca = *reinterpret_cast<const float4*>(Cs + d * 128 + c0);
        float4 cb = *reinterpret_cast<const float4*>(Cs + d * 128 + c0 + 4);
        float qv[8] = {qa.x, qa.y, qa.z, qa.w, qb.x, qb.y, qb.z, qb.w};
        float cv[8] = {ca.x, ca.y, ca.z, ca.w, cb.x, cb.y, cb.z, cb.w};
#pragma unroll
        for (int i = 0; i < 8; ++i)
#pragma unroll
            for (int j = 0; j < 8; ++j) acc[i][j] = fmaf(qv[i], cv[j], acc[i][j]);
    }

    float sc[8];
#pragma unroll
    for (int j = 0; j < 8; ++j) sc[j] = sqC[c0 + j];
#pragma unroll
    for (int i = 0; i < 8; ++i) {
        float4 w0, w1;
        w0.x = fmaf(-2.f, acc[i][0], sc[0]);
        w0.y = fmaf(-2.f, acc[i][1], sc[1]);
        w0.z = fmaf(-2.f, acc[i][2], sc[2]);
        w0.w = fmaf(-2.f, acc[i][3], sc[3]);
        w1.x = fmaf(-2.f, acc[i][4], sc[4]);
        w1.y = fmaf(-2.f, acc[i][5], sc[5]);
        w1.z = fmaf(-2.f, acc[i][6], sc[6]);
        w1.w = fmaf(-2.f, acc[i][7], sc[7]);
        float* dst = &g_dist[qbase + q0 + i][cbase + c0];
        *reinterpret_cast<float4*>(dst)     = w0;
        *reinterpret_cast<float4*>(dst + 4) = w1;
    }
}

// ---------------- kernel 4: warp-cooperative exact top-25 per query ----------
// One warp per query. Top-25 list distributed across lanes 0..24 (1 elem/lane).
// Stream row as float4; ballot vs warp-uniform tau; rare cooperative inserts.
__global__ void __launch_bounds__(256) k_select() {
    const int lane = threadIdx.x & 31;
    const int q    = blockIdx.x * 8 + (threadIdx.x >> 5);

    const float4* row4 = reinterpret_cast<const float4*>(g_dist[q]);

    float myval = 3.402823466e+38f;
    int   myidx = 0;
    float tau   = 3.402823466e+38f;

    for (int t = 0; t < NB / 128; ++t) {
        const int cb = t * 128 + lane * 4;
        float4 v = row4[t * 32 + lane];
        float dv4[4] = {v.x, v.y, v.z, v.w};
#pragma unroll
        for (int j = 0; j < 4; ++j) {
            int c = cb + j;
            float d = dv4[j];
            bool pass = (d < tau) && (c != q);
            unsigned mask = __ballot_sync(FULLM, pass);
            while (mask) {
                int src = __ffs(mask) - 1;
                mask &= mask - 1;
                float dv = __shfl_sync(FULLM, d, src);
                int   ci = __shfl_sync(FULLM, c, src);
                // warp argmax over the 25 list lanes (ties -> lower lane)
                float mv = (lane < KNN) ? myval : -3.402823466e+38f;
                int   ml = lane;
#pragma unroll
                for (int off = 16; off; off >>= 1) {
                    float ov = __shfl_xor_sync(FULLM, mv, off);
                    int   ol = __shfl_xor_sync(FULLM, ml, off);
                    if (ov > mv || (ov == mv && ol < ml)) { mv = ov; ml = ol; }
                }
                if (dv < mv) {
                    if (lane == ml) { myval = dv; myidx = ci; }
                    // recompute tau = new max of list
                    float u = (lane < KNN) ? myval : -3.402823466e+38f;
#pragma unroll
                    for (int off = 16; off; off >>= 1)
                        u = fmaxf(u, __shfl_xor_sync(FULLM, u, off));
                    tau = u;
                }
            }
        }
    }
    if (lane < KNN) g_nbrs[q][lane] = myidx;
}

// ---------------- kernel 5: per-point TSA term (warp per point) --------------
// P=1: sum((Pz-Px)^2) = 2 - 2*(u.v)^2 with u,v unit top-eigenvectors.
#define TSA_WPB 8
__global__ void __launch_bounds__(256) k_tsa(const float* __restrict__ latent,
                                             const float* __restrict__ raw) {
    __shared__ float s_pts[TSA_WPB][KNN][ND];
    __shared__ float s_A[TSA_WPB][16 * 17];
    __shared__ float s_B[TSA_WPB][16 * 17];
    __shared__ float s_u[TSA_WPB][16];
    __shared__ float s_v[TSA_WPB][16];
    __shared__ float s_mu[TSA_WPB][16];
    __shared__ int   s_nb[TSA_WPB][KNN];

    const int w = threadIdx.x >> 5, lane = threadIdx.x & 31;
    const int i = blockIdx.x * TSA_WPB + w;

    if (lane < KNN) s_nb[w][lane] = g_nbrs[i][lane];
    __syncwarp();

    for (int p = 0; p < 2; ++p) {
        const float* src = p ? raw : latent;
        float* uvec = p ? s_v[w] : s_u[w];

        for (int idx = lane; idx < KNN * ND; idx += 32) {
            int k = idx >> 4, d = idx & 15;
            s_pts[w][k][d] = src[(size_t)s_nb[w][k] * ND + d];
        }
        __syncwarp();
        if (lane < 16) {
            float m = 0.f;
#pragma unroll
            for (int k = 0; k < KNN; ++k) m += s_pts[w][k][lane];
            s_mu[w][lane] = m * (1.f / KNN);
        }
        __syncwarp();
        for (int idx = lane; idx < KNN * ND; idx += 32) {
            int k = idx >> 4, d = idx & 15;
            s_pts[w][k][d] -= s_mu[w][d];
        }
        __syncwarp();
        for (int e = lane; e < 256; e += 32) {
            int a = e >> 4, b = e & 15;
            float s = 0.f;
#pragma unroll
            for (int k = 0; k < KNN; ++k) s = fmaf(s_pts[w][k][a], s_pts[w][k][b], s);
            s_A[w][a * 17 + b] = s;
        }
        __syncwarp();

        float* Ain = s_A[w];
        float* Aou = s_B[w];
#pragma unroll 1
        for (int sq = 0; sq < 8; ++sq) {
            for (int e = lane; e < 256; e += 32) {
                int a = e >> 4, b = e & 15;
                float s = 0.f;
#pragma unroll
                for (int k = 0; k < 16; ++k) s = fmaf(Ain[a * 17 + k], Ain[k * 17 + b], s);
                Aou[a * 17 + b] = s;
            }
            __syncwarp();
            float dv = (lane < 16) ? Aou[lane * 17 + lane] : 0.f;
#pragma unroll
            for (int off = 16; off; off >>= 1)
                dv = fmaxf(dv, __shfl_xor_sync(FULLM, dv, off));
            float inv = 1.f / dv;
            for (int e = lane; e < 256; e += 32) {
                int a = e >> 4, b = e & 15;
                Aou[a * 17 + b] *= inv;
            }
            __syncwarp();
            float* tmp = Ain; Ain = Aou; Aou = tmp;
        }

        float bv = (lane < 16) ? Ain[lane * 17 + lane] : -1.f;
        int   bx = (lane < 16) ? lane : 1000;
#pragma unroll
        for (int off = 16; off; off >>= 1) {
            float ov = __shfl_xor_sync(FULLM, bv, off);
            int   oi = __shfl_xor_sync(FULLM, bx, off);
            if (ov > bv || (ov == bv && oi < bx)) { bv = ov; bx = oi; }
        }
        float uv = (lane < 16) ? Ain[lane * 17 + bx] : 0.f;
        float ss = uv * uv;
#pragma unroll
        for (int off = 16; off; off >>= 1) ss += __shfl_xor_sync(FULLM, ss, off);
        float rn = rsqrtf(ss);
        if (lane < 16) uvec[lane] = uv * rn;
        __syncwarp();
    }

    float pd = (lane < 16) ? s_u[w][lane] * s_v[w][lane] : 0.f;
#pragma unroll
    for (int off = 16; off; off >>= 1) pd += __shfl_xor_sync(FULLM, pd, off);
    if (lane == 0) {
        float term = fmaf(-2.f * pd, pd, 2.f);
        atomicAdd(&g_acc_tsa, term);
    }
}

// ---------------- kernel 6: finalize ----------------
__global__ void k_final(float* __restrict__ out) {
    out[0] = g_acc_recon * (1.f / (NB * ND)) + LAMBDA_TSA * g_acc_tsa * (1.f / NB);
}

// ---------------- launcher (kernel launches only; graph-capturable) ----------
extern "C" void kernel_launch(void* const* d_in, const int* in_sizes, int n_in,
                              void* d_out, int out_size) {
    const float* outputs = (const float*)d_in[0];
    const float* targets = (const float*)d_in[1];
    const float* latent  = (const float*)d_in[2];
    const float* raw     = (const float*)d_in[3];
    float* out = (float*)d_out;

    k_setup<<<NB / 256, 256>>>(raw);
    k_recon<<<64, 256>>>(outputs, targets);
    k_dist<<<dim3(NB / 128, NB / 128), 256>>>(raw);
    k_select<<<NB / 8, 256>>>();
    k_tsa<<<NB / TSA_WPB, 256>>>(latent, raw);
    k_final<<<1, 1>>>(out);
}

// round 6
// speedup vs baseline: 27.5178x; 1.2199x over previous
#include <cuda_runtime.h>
#include <math.h>

#define NB 16384
#define ND 16
#define KNN 25
#define LAMBDA_TSA 0.1f
#define FULLM 0xffffffffu
#define FLTMAX 3.402823466e+38f

#define QPW 4                 // queries per warp
#define WPB 8                 // warps per block
#define QPB (QPW * WPB)       // 32 queries per block
#define CTILE 128             // candidates per smem tile

// ---------------- device scratch (no allocations allowed) ----------------
__device__ float g_sq[NB];
__device__ int   g_nbrs[NB][KNN];
__device__ float g_acc_recon;
__device__ float g_acc_tsa;

// ---------------- kernel 1: squared norms + zero accumulators ----------------
__global__ void k_setup(const float* __restrict__ raw) {
    int i = blockIdx.x * blockDim.x + threadIdx.x;
    if (i < NB) {
        const float4* r4 = reinterpret_cast<const float4*>(raw + (size_t)i * ND);
        float s = 0.f;
#pragma unroll
        for (int j = 0; j < 4; ++j) {
            float4 v = r4[j];
            s = fmaf(v.x, v.x, s); s = fmaf(v.y, v.y, s);
            s = fmaf(v.z, v.z, s); s = fmaf(v.w, v.w, s);
        }
        g_sq[i] = s;
    }
    if (i == 0) { g_acc_recon = 0.f; g_acc_tsa = 0.f; }
}

// ---------------- kernel 2: recon MSE sum ----------------
__global__ void k_recon(const float* __restrict__ o, const float* __restrict__ t) {
    const float4* o4 = reinterpret_cast<const float4*>(o);
    const float4* t4 = reinterpret_cast<const float4*>(t);
    const int n4 = NB * ND / 4;
    float s = 0.f;
    for (int idx = blockIdx.x * blockDim.x + threadIdx.x; idx < n4;
         idx += gridDim.x * blockDim.x) {
        float4 a = o4[idx], b = t4[idx];
        float dx = a.x - b.x, dy = a.y - b.y, dz = a.z - b.z, dw = a.w - b.w;
        s = fmaf(dx, dx, s); s = fmaf(dy, dy, s);
        s = fmaf(dz, dz, s); s = fmaf(dw, dw, s);
    }
#pragma unroll
    for (int off = 16; off; off >>= 1) s += __shfl_xor_sync(FULLM, s, off);
    __shared__ float ws[8];
    int lane = threadIdx.x & 31, wid = threadIdx.x >> 5;
    if (lane == 0) ws[wid] = s;
    __syncthreads();
    if (threadIdx.x == 0) {
        float tot = 0.f;
#pragma unroll
        for (int k = 0; k < 8; ++k) tot += ws[k];
        atomicAdd(&g_acc_recon, tot);
    }
}

// ---------------- kernel 3: fused distance GEMM + warp-cooperative top-25 ----
// One warp owns QPW=4 queries (q-vectors in registers). Candidates streamed
// through a d-major smem tile; 1 scalar LDS feeds 4 FMAs. Top-25 lists live
// distributed across lanes 0..24 (one element per lane per query). Ballot
// against warp-uniform tau; inserts are rare warp-cooperative argmax swaps.
__global__ void __launch_bounds__(256) k_knn(const float* __restrict__ raw) {
    __shared__ float Cs[ND * CTILE];   // d-major candidate tile
    __shared__ float sqC[CTILE];

    const int tid  = threadIdx.x;
    const int lane = tid & 31;
    const int w    = tid >> 5;
    const int qb   = blockIdx.x * QPB + w * QPW;   // first query of this warp
    const float4* raw4 = reinterpret_cast<const float4*>(raw);

    // query vectors in registers (warp-uniform broadcast loads)
    float qv[QPW][ND];
#pragma unroll
    for (int j = 0; j < QPW; ++j)
#pragma unroll
        for (int d = 0; d < ND; ++d)
            qv[j][d] = __ldg(raw + (size_t)(qb + j) * ND + d);

    float lv[QPW]; int li[QPW]; float tau[QPW];
#pragma unroll
    for (int j = 0; j < QPW; ++j) { lv[j] = FLTMAX; li[j] = 0; tau[j] = FLTMAX; }

    for (int t = 0; t < NB / CTILE; ++t) {
        const int cbase = t * CTILE;
        __syncthreads();   // previous sub-loop LDS reads complete
        // cooperative load & transpose candidate tile (2 float4 per thread)
        for (int f = tid; f < CTILE * 4; f += 256) {
            int c = f >> 2, dc = f & 3;
            float4 v = raw4[(size_t)(cbase + c) * 4 + dc];
            Cs[(dc * 4 + 0) * CTILE + c] = v.x;
            Cs[(dc * 4 + 1) * CTILE + c] = v.y;
            Cs[(dc * 4 + 2) * CTILE + c] = v.z;
            Cs[(dc * 4 + 3) * CTILE + c] = v.w;
        }
        if (tid < CTILE) sqC[tid] = g_sq[cbase + tid];
        __syncthreads();

#pragma unroll 1
        for (int sub = 0; sub < CTILE / 32; ++sub) {
            const int cloc = sub * 32 + lane;
            const int cg   = cbase + cloc;

            float acc[QPW];
#pragma unroll
            for (int j = 0; j < QPW; ++j) acc[j] = 0.f;
#pragma unroll
            for (int d = 0; d < ND; ++d) {
                float cvv = Cs[d * CTILE + cloc];    // conflict-free scalar LDS
#pragma unroll
                for (int j = 0; j < QPW; ++j) acc[j] = fmaf(qv[j][d], cvv, acc[j]);
            }
            const float scv = sqC[cloc];
            float d2[QPW];
            unsigned pbits = 0;
#pragma unroll
            for (int j = 0; j < QPW; ++j) {
                d2[j] = fmaf(-2.f, acc[j], scv);
                if (d2[j] < tau[j] && cg != qb + j) pbits |= (1u << j);
            }
            // single combined ballot: skip all insert work in the common case
            if (__ballot_sync(FULLM, pbits != 0u)) {
#pragma unroll
                for (int j = 0; j < QPW; ++j) {
                    unsigned mask = __ballot_sync(FULLM, (pbits >> j) & 1u);
                    while (mask) {
                        int src = __ffs(mask) - 1;
                        mask &= mask - 1;
                        float dv = __shfl_sync(FULLM, d2[j], src);
                        int   ci = __shfl_sync(FULLM, cg, src);
                        // warp argmax over the 25 list lanes
                        float mv = (lane < KNN) ? lv[j] : -FLTMAX;
                        int   ml = lane;
#pragma unroll
                        for (int off = 16; off; off >>= 1) {
                            float ov = __shfl_xor_sync(FULLM, mv, off);
                            int   ol = __shfl_xor_sync(FULLM, ml, off);
                            if (ov > mv || (ov == mv && ol < ml)) { mv = ov; ml = ol; }
                        }
                        if (dv < mv) {      // warp-uniform
                            if (lane == ml) { lv[j] = dv; li[j] = ci; }
                            float u = (lane < KNN) ? lv[j] : -FLTMAX;
#pragma unroll
                            for (int off = 16; off; off >>= 1)
                                u = fmaxf(u, __shfl_xor_sync(FULLM, u, off));
                            tau[j] = u;
                        }
                    }
                }
            }
        }
    }

    if (lane < KNN) {
#pragma unroll
        for (int j = 0; j < QPW; ++j) g_nbrs[qb + j][lane] = li[j];
    }
}

// ---------------- kernel 4: per-point TSA term (warp per point) --------------
// P=1: sum((Pz-Px)^2) = 2 - 2*(u.v)^2 with u,v unit top-eigenvectors.
#define TSA_WPB 8
__global__ void __launch_bounds__(256) k_tsa(const float* __restrict__ latent,
                                             const float* __restrict__ raw) {
    __shared__ float s_pts[TSA_WPB][KNN][ND];
    __shared__ float s_A[TSA_WPB][16 * 17];
    __shared__ float s_B[TSA_WPB][16 * 17];
    __shared__ float s_u[TSA_WPB][16];
    __shared__ float s_v[TSA_WPB][16];
    __shared__ float s_mu[TSA_WPB][16];
    __shared__ int   s_nb[TSA_WPB][KNN];

    const int w = threadIdx.x >> 5, lane = threadIdx.x & 31;
    const int i = blockIdx.x * TSA_WPB + w;

    if (lane < KNN) s_nb[w][lane] = g_nbrs[i][lane];
    __syncwarp();

    for (int p = 0; p < 2; ++p) {
        const float* src = p ? raw : latent;
        float* uvec = p ? s_v[w] : s_u[w];

        for (int idx = lane; idx < KNN * ND; idx += 32) {
            int k = idx >> 4, d = idx & 15;
            s_pts[w][k][d] = src[(size_t)s_nb[w][k] * ND + d];
        }
        __syncwarp();
        if (lane < 16) {
            float m = 0.f;
#pragma unroll
            for (int k = 0; k < KNN; ++k) m += s_pts[w][k][lane];
            s_mu[w][lane] = m * (1.f / KNN);
        }
        __syncwarp();
        for (int idx = lane; idx < KNN * ND; idx += 32) {
            int k = idx >> 4, d = idx & 15;
            s_pts[w][k][d] -= s_mu[w][d];
        }
        __syncwarp();
        for (int e = lane; e < 256; e += 32) {
            int a = e >> 4, b = e & 15;
            float s = 0.f;
#pragma unroll
            for (int k = 0; k < KNN; ++k) s = fmaf(s_pts[w][k][a], s_pts[w][k][b], s);
            s_A[w][a * 17 + b] = s;
        }
        __syncwarp();

        float* Ain = s_A[w];
        float* Aou = s_B[w];
#pragma unroll 1
        for (int sq = 0; sq < 8; ++sq) {
            for (int e = lane; e < 256; e += 32) {
                int a = e >> 4, b = e & 15;
                float s = 0.f;
#pragma unroll
                for (int k = 0; k < 16; ++k) s = fmaf(Ain[a * 17 + k], Ain[k * 17 + b], s);
                Aou[a * 17 + b] = s;
            }
            __syncwarp();
            float dv = (lane < 16) ? Aou[lane * 17 + lane] : 0.f;
#pragma unroll
            for (int off = 16; off; off >>= 1)
                dv = fmaxf(dv, __shfl_xor_sync(FULLM, dv, off));
            float inv = 1.f / dv;
            for (int e = lane; e < 256; e += 32) {
                int a = e >> 4, b = e & 15;
                Aou[a * 17 + b] *= inv;
            }
            __syncwarp();
            float* tmp = Ain; Ain = Aou; Aou = tmp;
        }

        float bv = (lane < 16) ? Ain[lane * 17 + lane] : -1.f;
        int   bx = (lane < 16) ? lane : 1000;
#pragma unroll
        for (int off = 16; off; off >>= 1) {
            float ov = __shfl_xor_sync(FULLM, bv, off);
            int   oi = __shfl_xor_sync(FULLM, bx, off);
            if (ov > bv || (ov == bv && oi < bx)) { bv = ov; bx = oi; }
        }
        float uv = (lane < 16) ? Ain[lane * 17 + bx] : 0.f;
        float ss = uv * uv;
#pragma unroll
        for (int off = 16; off; off >>= 1) ss += __shfl_xor_sync(FULLM, ss, off);
        float rn = rsqrtf(ss);
        if (lane < 16) uvec[lane] = uv * rn;
        __syncwarp();
    }

    float pd = (lane < 16) ? s_u[w][lane] * s_v[w][lane] : 0.f;
#pragma unroll
    for (int off = 16; off; off >>= 1) pd += __shfl_xor_sync(FULLM, pd, off);
    if (lane == 0) {
        float term = fmaf(-2.f * pd, pd, 2.f);
        atomicAdd(&g_acc_tsa, term);
    }
}

// ---------------- kernel 5: finalize ----------------
__global__ void k_final(float* __restrict__ out) {
    out[0] = g_acc_recon * (1.f / (NB * ND)) + LAMBDA_TSA * g_acc_tsa * (1.f / NB);
}

// ---------------- launcher (kernel launches only; graph-capturable) ----------
extern "C" void kernel_launch(void* const* d_in, const int* in_sizes, int n_in,
                              void* d_out, int out_size) {
    const float* outputs = (const float*)d_in[0];
    const float* targets = (const float*)d_in[1];
    const float* latent  = (const float*)d_in[2];
    const float* raw     = (const float*)d_in[3];
    float* out = (float*)d_out;

    k_setup<<<NB / 256, 256>>>(raw);
    k_recon<<<64, 256>>>(outputs, targets);
    k_knn<<<NB / QPB, 256>>>(raw);
    k_tsa<<<NB / TSA_WPB, 256>>>(latent, raw);
    k_final<<<1, 1>>>(out);
}

// round 7
// speedup vs baseline: 34.3116x; 1.2469x over previous
#include <cuda_runtime.h>
#include <math.h>

#define NB 16384
#define ND 16
#define KNN 25
#define LAMBDA_TSA 0.1f
#define FULLM 0xffffffffu
#define FLTMAX 3.402823466e+38f

#define QPW 2                 // queries per warp
#define WPB 8                 // warps per block
#define QPB (QPW * WPB)       // 16 queries per block
#define CTILE 128             // candidates per smem tile
#define CSTR 129              // padded smem stride (conflict-free transpose)

// ---------------- device scratch (no allocations allowed) ----------------
__device__ float g_sq[NB];
__device__ int   g_nbrs[NB][KNN];
__device__ float g_acc_recon;
__device__ float g_acc_tsa;

// ---------------- kernel 1: squared norms + zero accumulators ----------------
__global__ void k_setup(const float* __restrict__ raw) {
    int i = blockIdx.x * blockDim.x + threadIdx.x;
    if (i < NB) {
        const float4* r4 = reinterpret_cast<const float4*>(raw + (size_t)i * ND);
        float s = 0.f;
#pragma unroll
        for (int j = 0; j < 4; ++j) {
            float4 v = r4[j];
            s = fmaf(v.x, v.x, s); s = fmaf(v.y, v.y, s);
            s = fmaf(v.z, v.z, s); s = fmaf(v.w, v.w, s);
        }
        g_sq[i] = s;
    }
    if (i == 0) { g_acc_recon = 0.f; g_acc_tsa = 0.f; }
}

// ---------------- kernel 2: recon MSE sum ----------------
__global__ void k_recon(const float* __restrict__ o, const float* __restrict__ t) {
    const float4* o4 = reinterpret_cast<const float4*>(o);
    const float4* t4 = reinterpret_cast<const float4*>(t);
    const int n4 = NB * ND / 4;
    float s = 0.f;
    for (int idx = blockIdx.x * blockDim.x + threadIdx.x; idx < n4;
         idx += gridDim.x * blockDim.x) {
        float4 a = o4[idx], b = t4[idx];
        float dx = a.x - b.x, dy = a.y - b.y, dz = a.z - b.z, dw = a.w - b.w;
        s = fmaf(dx, dx, s); s = fmaf(dy, dy, s);
        s = fmaf(dz, dz, s); s = fmaf(dw, dw, s);
    }
#pragma unroll
    for (int off = 16; off; off >>= 1) s += __shfl_xor_sync(FULLM, s, off);
    __shared__ float ws[8];
    int lane = threadIdx.x & 31, wid = threadIdx.x >> 5;
    if (lane == 0) ws[wid] = s;
    __syncthreads();
    if (threadIdx.x == 0) {
        float tot = 0.f;
#pragma unroll
        for (int k = 0; k < 8; ++k) tot += ws[k];
        atomicAdd(&g_acc_recon, tot);
    }
}

// combined max+argmax over list lanes (<KNN); all lanes get the result
__device__ __forceinline__ void maxreduce25(float v, int lane, float& outv, int& outl) {
    float mv = (lane < KNN) ? v : -FLTMAX;
    int   ml = lane;
#pragma unroll
    for (int off = 16; off; off >>= 1) {
        float ov = __shfl_xor_sync(FULLM, mv, off);
        int   ol = __shfl_xor_sync(FULLM, ml, off);
        if (ov > mv || (ov == mv && ol < ml)) { mv = ov; ml = ol; }
    }
    outv = mv; outl = ml;
}

// ---------------- kernel 3: fused distance GEMM + warp-cooperative top-25 ----
// One warp owns QPW=2 queries in registers. Candidates streamed through a
// d-major smem tile (1 LDS feeds 2 FMAs). Top-25 distributed across lanes
// 0..24; (tau, mlane) maintained so each insert costs one combined reduce.
// First 32 candidates seed the lists in one shot (lane k holds candidate k).
__global__ void __launch_bounds__(256) k_knn(const float* __restrict__ raw) {
    __shared__ float Cs[ND * CSTR];
    __shared__ float sqC[CTILE];

    const int tid  = threadIdx.x;
    const int lane = tid & 31;
    const int w    = tid >> 5;
    const int qb   = blockIdx.x * QPB + w * QPW;
    const float4* raw4 = reinterpret_cast<const float4*>(raw);

    float qv[QPW][ND];
#pragma unroll
    for (int j = 0; j < QPW; ++j)
#pragma unroll
        for (int d = 0; d < ND; ++d)
            qv[j][d] = __ldg(raw + (size_t)(qb + j) * ND + d);

    float lv[QPW]; int li[QPW]; float tau[QPW]; int mlane[QPW];
#pragma unroll
    for (int j = 0; j < QPW; ++j) { lv[j] = FLTMAX; li[j] = 0; tau[j] = FLTMAX; mlane[j] = 0; }

    for (int t = 0; t < NB / CTILE; ++t) {
        const int cbase = t * CTILE;
        __syncthreads();
        for (int f = tid; f < CTILE * 4; f += 256) {
            int c = f >> 2, dc = f & 3;
            float4 v = raw4[(size_t)(cbase + c) * 4 + dc];
            Cs[(dc * 4 + 0) * CSTR + c] = v.x;
            Cs[(dc * 4 + 1) * CSTR + c] = v.y;
            Cs[(dc * 4 + 2) * CSTR + c] = v.z;
            Cs[(dc * 4 + 3) * CSTR + c] = v.w;
        }
        if (tid < CTILE) sqC[tid] = g_sq[cbase + tid];
        __syncthreads();

#pragma unroll 1
        for (int sub = 0; sub < CTILE / 32; ++sub) {
            const int cloc = sub * 32 + lane;
            const int cg   = cbase + cloc;

            float acc[QPW];
#pragma unroll
            for (int j = 0; j < QPW; ++j) acc[j] = 0.f;
#pragma unroll
            for (int d = 0; d < ND; ++d) {
                float cvv = Cs[d * CSTR + cloc];
#pragma unroll
                for (int j = 0; j < QPW; ++j) acc[j] = fmaf(qv[j][d], cvv, acc[j]);
            }
            const float scv = sqC[cloc];
            float d2[QPW];
#pragma unroll
            for (int j = 0; j < QPW; ++j) d2[j] = fmaf(-2.f, acc[j], scv);

            if (t == 0 && sub == 0) {
                // seed: lane k's candidate k -> list slot k (self -> FLTMAX hole)
#pragma unroll
                for (int j = 0; j < QPW; ++j) {
                    lv[j] = (lane < KNN && cg != qb + j) ? d2[j] : FLTMAX;
                    li[j] = cg;
                    maxreduce25(lv[j], lane, tau[j], mlane[j]);
                }
                // candidates 25..31 go through the normal insert path
                unsigned pb = 0;
#pragma unroll
                for (int j = 0; j < QPW; ++j)
                    if (lane >= KNN && d2[j] < tau[j] && cg != qb + j) pb |= (1u << j);
#pragma unroll
                for (int j = 0; j < QPW; ++j) {
                    unsigned mask = __ballot_sync(FULLM, (pb >> j) & 1u);
                    while (mask) {
                        int src = __ffs(mask) - 1; mask &= mask - 1;
                        float dv = __shfl_sync(FULLM, d2[j], src);
                        int   ci = __shfl_sync(FULLM, cg, src);
                        if (dv < tau[j]) {
                            if (lane == mlane[j]) { lv[j] = dv; li[j] = ci; }
                            maxreduce25(lv[j], lane, tau[j], mlane[j]);
                        }
                    }
                }
                continue;
            }

            unsigned pb = 0;
#pragma unroll
            for (int j = 0; j < QPW; ++j)
                if (d2[j] < tau[j] && cg != qb + j) pb |= (1u << j);
            if (__ballot_sync(FULLM, pb)) {
#pragma unroll
                for (int j = 0; j < QPW; ++j) {
                    unsigned mask = __ballot_sync(FULLM, (pb >> j) & 1u);
                    while (mask) {
                        int src = __ffs(mask) - 1; mask &= mask - 1;
                        float dv = __shfl_sync(FULLM, d2[j], src);
                        int   ci = __shfl_sync(FULLM, cg, src);
                        if (dv < tau[j]) {   // tau may have tightened in this drain
                            if (lane == mlane[j]) { lv[j] = dv; li[j] = ci; }
                            maxreduce25(lv[j], lane, tau[j], mlane[j]);
                        }
                    }
                }
            }
        }
    }

    if (lane < KNN) {
#pragma unroll
        for (int j = 0; j < QPW; ++j) g_nbrs[qb + j][lane] = li[j];
    }
}

// ---------------- kernel 4: per-point TSA term (warp per point) --------------
// P=1: sum((Pz-Px)^2) = 2 - 2*(u.v)^2 with u,v unit top-eigenvectors.
#define TSA_WPB 8
__global__ void __launch_bounds__(256) k_tsa(const float* __restrict__ latent,
                                             const float* __restrict__ raw) {
    __shared__ float s_pts[TSA_WPB][KNN][ND];
    __shared__ float s_A[TSA_WPB][16 * 17];
    __shared__ float s_B[TSA_WPB][16 * 17];
    __shared__ float s_u[TSA_WPB][16];
    __shared__ float s_v[TSA_WPB][16];
    __shared__ float s_mu[TSA_WPB][16];
    __shared__ int   s_nb[TSA_WPB][KNN];

    const int w = threadIdx.x >> 5, lane = threadIdx.x & 31;
    const int i = blockIdx.x * TSA_WPB + w;

    if (lane < KNN) s_nb[w][lane] = g_nbrs[i][lane];
    __syncwarp();

    for (int p = 0; p < 2; ++p) {
        const float* src = p ? raw : latent;
        float* uvec = p ? s_v[w] : s_u[w];

        for (int idx = lane; idx < KNN * ND; idx += 32) {
            int k = idx >> 4, d = idx & 15;
            s_pts[w][k][d] = src[(size_t)s_nb[w][k] * ND + d];
        }
        __syncwarp();
        if (lane < 16) {
            float m = 0.f;
#pragma unroll
            for (int k = 0; k < KNN; ++k) m += s_pts[w][k][lane];
            s_mu[w][lane] = m * (1.f / KNN);
        }
        __syncwarp();
        for (int idx = lane; idx < KNN * ND; idx += 32) {
            int k = idx >> 4, d = idx & 15;
            s_pts[w][k][d] -= s_mu[w][d];
        }
        __syncwarp();
        for (int e = lane; e < 256; e += 32) {
            int a = e >> 4, b = e & 15;
            float s = 0.f;
#pragma unroll
            for (int k = 0; k < KNN; ++k) s = fmaf(s_pts[w][k][a], s_pts[w][k][b], s);
            s_A[w][a * 17 + b] = s;
        }
        __syncwarp();

        float* Ain = s_A[w];
        float* Aou = s_B[w];
#pragma unroll 1
        for (int sq = 0; sq < 8; ++sq) {
            for (int e = lane; e < 256; e += 32) {
                int a = e >> 4, b = e & 15;
                float s = 0.f;
#pragma unroll
                for (int k = 0; k < 16; ++k) s = fmaf(Ain[a * 17 + k], Ain[k * 17 + b], s);
                Aou[a * 17 + b] = s;
            }
            __syncwarp();
            float dv = (lane < 16) ? Aou[lane * 17 + lane] : 0.f;
#pragma unroll
            for (int off = 16; off; off >>= 1)
                dv = fmaxf(dv, __shfl_xor_sync(FULLM, dv, off));
            float inv = 1.f / dv;
            for (int e = lane; e < 256; e += 32) {
                int a = e >> 4, b = e & 15;
                Aou[a * 17 + b] *= inv;
            }
            __syncwarp();
            float* tmp = Ain; Ain = Aou; Aou = tmp;
        }

        float bv = (lane < 16) ? Ain[lane * 17 + lane] : -1.f;
        int   bx = (lane < 16) ? lane : 1000;
#pragma unroll
        for (int off = 16; off; off >>= 1) {
            float ov = __shfl_xor_sync(FULLM, bv, off);
            int   oi = __shfl_xor_sync(FULLM, bx, off);
            if (ov > bv || (ov == bv && oi < bx)) { bv = ov; bx = oi; }
        }
        float uv = (lane < 16) ? Ain[lane * 17 + bx] : 0.f;
        float ss = uv * uv;
#pragma unroll
        for (int off = 16; off; off >>= 1) ss += __shfl_xor_sync(FULLM, ss, off);
        float rn = rsqrtf(ss);
        if (lane < 16) uvec[lane] = uv * rn;
        __syncwarp();
    }

    float pd = (lane < 16) ? s_u[w][lane] * s_v[w][lane] : 0.f;
#pragma unroll
    for (int off = 16; off; off >>= 1) pd += __shfl_xor_sync(FULLM, pd, off);
    if (lane == 0) {
        float term = fmaf(-2.f * pd, pd, 2.f);
        atomicAdd(&g_acc_tsa, term);
    }
}

// ---------------- kernel 5: finalize ----------------
__global__ void k_final(float* __restrict__ out) {
    out[0] = g_acc_recon * (1.f / (NB * ND)) + LAMBDA_TSA * g_acc_tsa * (1.f / NB);
}

// ---------------- launcher (kernel launches only; graph-capturable) ----------
extern "C" void kernel_launch(void* const* d_in, const int* in_sizes, int n_in,
                              void* d_out, int out_size) {
    const float* outputs = (const float*)d_in[0];
    const float* targets = (const float*)d_in[1];
    const float* latent  = (const float*)d_in[2];
    const float* raw     = (const float*)d_in[3];
    float* out = (float*)d_out;

    k_setup<<<NB / 256, 256>>>(raw);
    k_recon<<<64, 256>>>(outputs, targets);
    k_knn<<<NB / QPB, 256>>>(raw);
    k_tsa<<<NB / TSA_WPB, 256>>>(latent, raw);
    k_final<<<1, 1>>>(out);
}

// round 8
// speedup vs baseline: 37.6025x; 1.0959x over previous
#include <cuda_runtime.h>
#include <math.h>

#define NB 16384
#define ND 16
#define KNN 25
#define LAMBDA_TSA 0.1f
#define FULLM 0xffffffffu
#define FLTMAX 3.402823466e+38f

#define QPW 2                 // queries per warp
#define WPB 8                 // warps per block
#define QPB (QPW * WPB)       // 16 queries per block
#define CTILE 128             // candidates per smem tile
#define CPAD 20               // padded row stride (16 data + sq + pad); 80B

// ---------------- device scratch (no allocations allowed) ----------------
__device__ float g_sq[NB];
__device__ int   g_nbrs[NB][KNN];
__device__ float g_acc_recon;
__device__ float g_acc_tsa;

// ---------------- kernel 1: squared norms + zero accumulators ----------------
__global__ void k_setup(const float* __restrict__ raw) {
    int i = blockIdx.x * blockDim.x + threadIdx.x;
    if (i < NB) {
        const float4* r4 = reinterpret_cast<const float4*>(raw + (size_t)i * ND);
        float s = 0.f;
#pragma unroll
        for (int j = 0; j < 4; ++j) {
            float4 v = r4[j];
            s = fmaf(v.x, v.x, s); s = fmaf(v.y, v.y, s);
            s = fmaf(v.z, v.z, s); s = fmaf(v.w, v.w, s);
        }
        g_sq[i] = s;
    }
    if (i == 0) { g_acc_recon = 0.f; g_acc_tsa = 0.f; }
}

// ---------------- kernel 2: recon MSE sum ----------------
__global__ void k_recon(const float* __restrict__ o, const float* __restrict__ t) {
    const float4* o4 = reinterpret_cast<const float4*>(o);
    const float4* t4 = reinterpret_cast<const float4*>(t);
    const int n4 = NB * ND / 4;
    float s = 0.f;
    for (int idx = blockIdx.x * blockDim.x + threadIdx.x; idx < n4;
         idx += gridDim.x * blockDim.x) {
        float4 a = o4[idx], b = t4[idx];
        float dx = a.x - b.x, dy = a.y - b.y, dz = a.z - b.z, dw = a.w - b.w;
        s = fmaf(dx, dx, s); s = fmaf(dy, dy, s);
        s = fmaf(dz, dz, s); s = fmaf(dw, dw, s);
    }
#pragma unroll
    for (int off = 16; off; off >>= 1) s += __shfl_xor_sync(FULLM, s, off);
    __shared__ float ws[8];
    int lane = threadIdx.x & 31, wid = threadIdx.x >> 5;
    if (lane == 0) ws[wid] = s;
    __syncthreads();
    if (threadIdx.x == 0) {
        float tot = 0.f;
#pragma unroll
        for (int k = 0; k < 8; ++k) tot += ws[k];
        atomicAdd(&g_acc_recon, tot);
    }
}

// combined max+argmax over list lanes (<KNN); all lanes get the result
__device__ __forceinline__ void maxreduce25(float v, int lane, float& outv, int& outl) {
    float mv = (lane < KNN) ? v : -FLTMAX;
    int   ml = lane;
#pragma unroll
    for (int off = 16; off; off >>= 1) {
        float ov = __shfl_xor_sync(FULLM, mv, off);
        int   ol = __shfl_xor_sync(FULLM, ml, off);
        if (ov > mv || (ov == mv && ol < ml)) { mv = ov; ml = ol; }
    }
    outv = mv; outl = ml;
}

// ---------------- kernel 3: fused distance GEMM + warp-cooperative top-25 ----
// Row-major padded candidate tile (80B rows -> conflict-free LDS.128); each
// lane reads its own candidate row (4x LDS.128 + sq in the padding). Register
// double-buffered tile loads. Distributed top-25 with (tau, mlane) state.
__global__ void __launch_bounds__(256) k_knn(const float* __restrict__ raw) {
    __shared__ float Cs[CTILE * CPAD];

    const int tid  = threadIdx.x;
    const int lane = tid & 31;
    const int w    = tid >> 5;
    const int qb   = blockIdx.x * QPB + w * QPW;
    const float4* raw4 = reinterpret_cast<const float4*>(raw);

    // per-thread tile-load coordinates (2 float4 per thread per tile)
    const int lc0 = tid >> 2,        ld0 = tid & 3;          // f = tid
    const int lc1 = (tid + 256) >> 2, ld1 = (tid + 256) & 3; // f = tid+256

    float qv[QPW][ND];
#pragma unroll
    for (int j = 0; j < QPW; ++j)
#pragma unroll
        for (int d = 0; d < ND; ++d)
            qv[j][d] = __ldg(raw + (size_t)(qb + j) * ND + d);

    float lv[QPW]; int li[QPW]; float tau[QPW]; int mlane[QPW];
#pragma unroll
    for (int j = 0; j < QPW; ++j) { lv[j] = FLTMAX; li[j] = 0; tau[j] = FLTMAX; mlane[j] = 0; }

    // prefetch tile 0
    float4 pf0 = raw4[(size_t)lc0 * 4 + ld0];
    float4 pf1 = raw4[(size_t)lc1 * 4 + ld1];
    float  psq = (tid < CTILE) ? g_sq[tid] : 0.f;

    for (int t = 0; t < NB / CTILE; ++t) {
        const int cbase = t * CTILE;
        __syncthreads();   // prior tile's LDS reads complete
        *reinterpret_cast<float4*>(&Cs[lc0 * CPAD + ld0 * 4]) = pf0;
        *reinterpret_cast<float4*>(&Cs[lc1 * CPAD + ld1 * 4]) = pf1;
        if (tid < CTILE) Cs[tid * CPAD + 16] = psq;
        __syncthreads();

        if (t + 1 < NB / CTILE) {   // prefetch next tile (overlaps compute)
            const int nb4 = (cbase + CTILE) * 4;
            pf0 = raw4[(size_t)nb4 + lc0 * 4 + ld0];
            pf1 = raw4[(size_t)nb4 + lc1 * 4 + ld1];
            if (tid < CTILE) psq = g_sq[cbase + CTILE + tid];
        }

#pragma unroll 1
        for (int sub = 0; sub < CTILE / 32; ++sub) {
            const int cloc = sub * 32 + lane;
            const int cg   = cbase + cloc;
            const float4* rp = reinterpret_cast<const float4*>(&Cs[cloc * CPAD]);
            const float4 c0 = rp[0], c1 = rp[1], c2 = rp[2], c3 = rp[3];
            const float scv = Cs[cloc * CPAD + 16];

            float d2[QPW];
#pragma unroll
            for (int j = 0; j < QPW; ++j) {
                float a = 0.f;
                a = fmaf(qv[j][0],  c0.x, a); a = fmaf(qv[j][1],  c0.y, a);
                a = fmaf(qv[j][2],  c0.z, a); a = fmaf(qv[j][3],  c0.w, a);
                a = fmaf(qv[j][4],  c1.x, a); a = fmaf(qv[j][5],  c1.y, a);
                a = fmaf(qv[j][6],  c1.z, a); a = fmaf(qv[j][7],  c1.w, a);
                a = fmaf(qv[j][8],  c2.x, a); a = fmaf(qv[j][9],  c2.y, a);
                a = fmaf(qv[j][10], c2.z, a); a = fmaf(qv[j][11], c2.w, a);
                a = fmaf(qv[j][12], c3.x, a); a = fmaf(qv[j][13], c3.y, a);
                a = fmaf(qv[j][14], c3.z, a); a = fmaf(qv[j][15], c3.w, a);
                d2[j] = fmaf(-2.f, a, scv);
            }

            if (t == 0 && sub == 0) {
                // seed: lane k's candidate k -> list slot k (self -> FLTMAX hole)
#pragma unroll
                for (int j = 0; j < QPW; ++j) {
                    lv[j] = (lane < KNN && cg != qb + j) ? d2[j] : FLTMAX;
                    li[j] = cg;
                    maxreduce25(lv[j], lane, tau[j], mlane[j]);
                }
                unsigned pb = 0;
#pragma unroll
                for (int j = 0; j < QPW; ++j)
                    if (lane >= KNN && d2[j] < tau[j] && cg != qb + j) pb |= (1u << j);
#pragma unroll
                for (int j = 0; j < QPW; ++j) {
                    unsigned mask = __ballot_sync(FULLM, (pb >> j) & 1u);
                    while (mask) {
                        int src = __ffs(mask) - 1; mask &= mask - 1;
                        float dv = __shfl_sync(FULLM, d2[j], src);
                        int   ci = __shfl_sync(FULLM, cg, src);
                        if (dv < tau[j]) {
                            if (lane == mlane[j]) { lv[j] = dv; li[j] = ci; }
                            maxreduce25(lv[j], lane, tau[j], mlane[j]);
                        }
                    }
                }
                continue;
            }

            unsigned pb = 0;
#pragma unroll
            for (int j = 0; j < QPW; ++j)
                if (d2[j] < tau[j] && cg != qb + j) pb |= (1u << j);
            if (__ballot_sync(FULLM, pb)) {
#pragma unroll
                for (int j = 0; j < QPW; ++j) {
                    unsigned mask = __ballot_sync(FULLM, (pb >> j) & 1u);
                    while (mask) {
                        int src = __ffs(mask) - 1; mask &= mask - 1;
                        float dv = __shfl_sync(FULLM, d2[j], src);
                        int   ci = __shfl_sync(FULLM, cg, src);
                        if (dv < tau[j]) {
                            if (lane == mlane[j]) { lv[j] = dv; li[j] = ci; }
                            maxreduce25(lv[j], lane, tau[j], mlane[j]);
                        }
                    }
                }
            }
        }
    }

    if (lane < KNN) {
#pragma unroll
        for (int j = 0; j < QPW; ++j) g_nbrs[qb + j][lane] = li[j];
    }
}

// ---------------- kernel 4: per-point TSA term (warp per point) --------------
// P=1: sum((Pz-Px)^2) = 2 - 2*(u.v)^2 with u,v unit top-eigenvectors.
#define TSA_WPB 8
__global__ void __launch_bounds__(256) k_tsa(const float* __restrict__ latent,
                                             const float* __restrict__ raw) {
    __shared__ float s_pts[TSA_WPB][KNN][ND];
    __shared__ float s_A[TSA_WPB][16 * 17];
    __shared__ float s_B[TSA_WPB][16 * 17];
    __shared__ float s_u[TSA_WPB][16];
    __shared__ float s_v[TSA_WPB][16];
    __shared__ float s_mu[TSA_WPB][16];
    __shared__ int   s_nb[TSA_WPB][KNN];

    const int w = threadIdx.x >> 5, lane = threadIdx.x & 31;
    const int i = blockIdx.x * TSA_WPB + w;

    if (lane < KNN) s_nb[w][lane] = g_nbrs[i][lane];
    __syncwarp();

    for (int p = 0; p < 2; ++p) {
        const float* src = p ? raw : latent;
        float* uvec = p ? s_v[w] : s_u[w];

        for (int idx = lane; idx < KNN * ND; idx += 32) {
            int k = idx >> 4, d = idx & 15;
            s_pts[w][k][d] = src[(size_t)s_nb[w][k] * ND + d];
        }
        __syncwarp();
        if (lane < 16) {
            float m = 0.f;
#pragma unroll
            for (int k = 0; k < KNN; ++k) m += s_pts[w][k][lane];
            s_mu[w][lane] = m * (1.f / KNN);
        }
        __syncwarp();
        for (int idx = lane; idx < KNN * ND; idx += 32) {
            int k = idx >> 4, d = idx & 15;
            s_pts[w][k][d] -= s_mu[w][d];
        }
        __syncwarp();
        for (int e = lane; e < 256; e += 32) {
            int a = e >> 4, b = e & 15;
            float s = 0.f;
#pragma unroll
            for (int k = 0; k < KNN; ++k) s = fmaf(s_pts[w][k][a], s_pts[w][k][b], s);
            s_A[w][a * 17 + b] = s;
        }
        __syncwarp();

        float* Ain = s_A[w];
        float* Aou = s_B[w];
#pragma unroll 1
        for (int sq = 0; sq < 8; ++sq) {
            for (int e = lane; e < 256; e += 32) {
                int a = e >> 4, b = e & 15;
                float s = 0.f;
#pragma unroll
                for (int k = 0; k < 16; ++k) s = fmaf(Ain[a * 17 + k], Ain[k * 17 + b], s);
                Aou[a * 17 + b] = s;
            }
            __syncwarp();
            float dv = (lane < 16) ? Aou[lane * 17 + lane] : 0.f;
#pragma unroll
            for (int off = 16; off; off >>= 1)
                dv = fmaxf(dv, __shfl_xor_sync(FULLM, dv, off));
            float inv = 1.f / dv;
            for (int e = lane; e < 256; e += 32) {
                int a = e >> 4, b = e & 15;
                Aou[a * 17 + b] *= inv;
            }
            __syncwarp();
            float* tmp = Ain; Ain = Aou; Aou = tmp;
        }

        float bv = (lane < 16) ? Ain[lane * 17 + lane] : -1.f;
        int   bx = (lane < 16) ? lane : 1000;
#pragma unroll
        for (int off = 16; off; off >>= 1) {
            float ov = __shfl_xor_sync(FULLM, bv, off);
            int   oi = __shfl_xor_sync(FULLM, bx, off);
            if (ov > bv || (ov == bv && oi < bx)) { bv = ov; bx = oi; }
        }
        float uv = (lane < 16) ? Ain[lane * 17 + bx] : 0.f;
        float ss = uv * uv;
#pragma unroll
        for (int off = 16; off; off >>= 1) ss += __shfl_xor_sync(FULLM, ss, off);
        float rn = rsqrtf(ss);
        if (lane < 16) uvec[lane] = uv * rn;
        __syncwarp();
    }

    float pd = (lane < 16) ? s_u[w][lane] * s_v[w][lane] : 0.f;
#pragma unroll
    for (int off = 16; off; off >>= 1) pd += __shfl_xor_sync(FULLM, pd, off);
    if (lane == 0) {
        float term = fmaf(-2.f * pd, pd, 2.f);
        atomicAdd(&g_acc_tsa, term);
    }
}

// ---------------- kernel 5: finalize ----------------
__global__ void k_final(float* __restrict__ out) {
    out[0] = g_acc_recon * (1.f / (NB * ND)) + LAMBDA_TSA * g_acc_tsa * (1.f / NB);
}

// ---------------- launcher (kernel launches only; graph-capturable) ----------
extern "C" void kernel_launch(void* const* d_in, const int* in_sizes, int n_in,
                              void* d_out, int out_size) {
    const float* outputs = (const float*)d_in[0];
    const float* targets = (const float*)d_in[1];
    const float* latent  = (const float*)d_in[2];
    const float* raw     = (const float*)d_in[3];
    float* out = (float*)d_out;

    k_setup<<<NB / 256, 256>>>(raw);
    k_recon<<<64, 256>>>(outputs, targets);
    k_knn<<<NB / QPB, 256>>>(raw);
    k_tsa<<<NB / TSA_WPB, 256>>>(latent, raw);
    k_final<<<1, 1>>>(out);
}